// round 4
// baseline (speedup 1.0000x reference)
#include <cuda_runtime.h>
#include <cstdint>
#include <cstddef>

// Router: top-1 MoE routing with capacity constraint.
// Outputs (float32): dispatch[N,8,Ccap], combine[N,8,Ccap], z, aux, div, std
//
// 2 launches:
//   1) fill_token_kernel: blocks [0,TBLOCKS) do per-token softmax/argmax/keys/
//      loss partials (hidden under the fill); blocks [TBLOCKS,..) zero-fill the
//      805MB output at the DRAM-write roofline.
//   2) rank_scatter_kernel: fold partials, warp-parallel branchless stable rank,
//      sparse scatter of <=2*8192 nonzeros, scalar finalize.

#define E 8
#define MAXN 8192
#define NACC 55   // 0:z  1..8:psum  9..16:cnt  17..52:G(upper tri 36)  53:sum  54:sumsq
#define TBLOCKS 32
#define FBLOCKS 2368

__device__ unsigned long long g_fkey[MAXN];   // [e:3][p_bits:32][invidx:13]
__device__ float g_prob[MAXN];
__device__ float g_part[TBLOCKS][NACC];

// ------------------------------------------------------- fill + token ----
__global__ void fill_token_kernel(uint4* __restrict__ out, size_t n4,
                                  const float* __restrict__ logits, int N) {
    if (blockIdx.x < TBLOCKS) {
        // ---- token path: softmax/argmax + composite key + loss partials ----
        int i = blockIdx.x * blockDim.x + threadIdx.x;
        float vals[NACC];
#pragma unroll
        for (int k = 0; k < NACC; k++) vals[k] = 0.0f;

        if (i < N) {
            float4 r0 = reinterpret_cast<const float4*>(logits)[2 * i + 0];
            float4 r1 = reinterpret_cast<const float4*>(logits)[2 * i + 1];
            float raw[E] = {r0.x, r0.y, r0.z, r0.w, r1.x, r1.y, r1.z, r1.w};

            float l[E];
            float s = 0.f, s2 = 0.f;
#pragma unroll
            for (int j = 0; j < E; j++) {
                s  += raw[j];
                s2 += raw[j] * raw[j];
                float c = fminf(fmaxf(raw[j], -10.0f), 10.0f);
                l[j] = c / 1.5f;                 // IEEE div, matches JAX clip/temp
            }
            vals[53] = s;
            vals[54] = s2;

            // argmax (first max)
            float m = l[0]; int e = 0;
#pragma unroll
            for (int j = 1; j < E; j++) {
                if (l[j] > m) { m = l[j]; e = j; }
            }

            float sumexp = 0.f;
            float ex[E];
#pragma unroll
            for (int j = 0; j < E; j++) { ex[j] = expf(l[j] - m); sumexp += ex[j]; }
#pragma unroll
            for (int j = 0; j < E; j++) vals[1 + j] = ex[j] / sumexp;

            // static-index one-hot (no local-memory spill)
#pragma unroll
            for (int j = 0; j < E; j++) vals[9 + j] = (e == j) ? 1.0f : 0.0f;

            float p = 1.0f / sumexp;             // probs[argmax] exactly as JAX
            g_prob[i] = p;
            // key: expert | prob bits | inverted index (branchless stable desc sort)
            unsigned long long key = (unsigned long long)__float_as_uint(p);
            g_fkey[i] = ((unsigned long long)e << 45) | (key << 13)
                      | (unsigned long long)(unsigned)(MAXN - 1 - i);

            float lse = m + logf(sumexp);
            vals[0] = lse * lse;

            int t = 0;
#pragma unroll
            for (int a = 0; a < E; a++)
#pragma unroll
                for (int b = a; b < E; b++) vals[17 + t++] = l[a] * l[b];
        }

        int lane = threadIdx.x & 31;
        int wid  = threadIdx.x >> 5;
#pragma unroll
        for (int k = 0; k < NACC; k++) {
            float v = vals[k];
            v += __shfl_down_sync(0xffffffffu, v, 16);
            v += __shfl_down_sync(0xffffffffu, v, 8);
            v += __shfl_down_sync(0xffffffffu, v, 4);
            v += __shfl_down_sync(0xffffffffu, v, 2);
            v += __shfl_down_sync(0xffffffffu, v, 1);
            vals[k] = v;
        }
        __shared__ float sAcc[8][NACC];
        if (lane == 0) {
#pragma unroll
            for (int k = 0; k < NACC; k++) sAcc[wid][k] = vals[k];
        }
        __syncthreads();
        for (int k = threadIdx.x; k < NACC; k += blockDim.x) {
            float v = 0.f;
#pragma unroll
            for (int w = 0; w < 8; w++) v += sAcc[w][k];
            g_part[blockIdx.x][k] = v;   // fully overwritten each replay: no init
        }
    } else {
        // ---- fill path: DRAM-bound zero fill ----
        const uint4 z = make_uint4(0u, 0u, 0u, 0u);
        size_t i = (size_t)(blockIdx.x - TBLOCKS) * blockDim.x + threadIdx.x;
        size_t stride = (size_t)FBLOCKS * blockDim.x;
        for (; i < n4; i += stride) out[i] = z;
    }
}

// -------------------------------------------------------- rank + scatter ----
// Block: 256 threads = 8 warps; each warp owns 4 tokens, lanes split the j loop.
// rank_i = #{j : fkey_j > fkey_i && fkey_j < (e_i+1)<<45}  (branchless, stable)
__global__ void rank_scatter_kernel(float* __restrict__ dispatch_out,
                                    float* __restrict__ combine_out,
                                    float* __restrict__ scalars_out,
                                    int N, int Ccap) {
    extern __shared__ unsigned long long sk[];   // MAXN * 8B = 64KB
    __shared__ float sAccF[NACC];

    // block 0: fold loss partials in parallel (before syncthreads)
    if (blockIdx.x == 0 && threadIdx.x < NACC) {
        int k = threadIdx.x;
        float v = 0.f;
#pragma unroll
        for (int r = 0; r < TBLOCKS; r++) v += g_part[r][k];
        sAccF[k] = v;
    }

    for (int k = threadIdx.x; k < MAXN; k += blockDim.x)
        sk[k] = (k < N) ? g_fkey[k] : 0ull;      // 0 never counts (fk > fki fails)
    __syncthreads();

    int lane = threadIdx.x & 31;
    int wid  = threadIdx.x >> 5;
    int base = (blockIdx.x * 8 + wid) * 4;       // first of this warp's 4 tokens

    unsigned long long fki[4], up[4];
    int cnt[4] = {0, 0, 0, 0};
#pragma unroll
    for (int t = 0; t < 4; t++) {
        int tok = base + t;
        unsigned long long f = (tok < N) ? sk[tok] : ~0ull;  // ~0: counts nothing
        fki[t] = f;
        up[t]  = (((f >> 45) + 1ull) << 45);
    }

    int n32 = MAXN >> 5;                         // 256 iterations per lane
#pragma unroll 8
    for (int it = 0; it < n32; ++it) {
        unsigned long long fk = sk[it * 32 + lane];
#pragma unroll
        for (int t = 0; t < 4; t++)
            cnt[t] += (int)((fk > fki[t]) & (fk < up[t]));
    }

#pragma unroll
    for (int t = 0; t < 4; t++) {
        int v = cnt[t];
        v += __shfl_down_sync(0xffffffffu, v, 16);
        v += __shfl_down_sync(0xffffffffu, v, 8);
        v += __shfl_down_sync(0xffffffffu, v, 4);
        v += __shfl_down_sync(0xffffffffu, v, 2);
        v += __shfl_down_sync(0xffffffffu, v, 1);
        cnt[t] = __shfl_sync(0xffffffffu, v, 0);
    }

    if (lane < 4) {
        int tok = base + lane;
        int rank = cnt[lane];
        if (tok < N && rank < Ccap) {
            int e = (int)(fki[lane] >> 45);
            float p = g_prob[tok];
            size_t b = ((size_t)tok * E + e) * (size_t)Ccap + (size_t)rank;
            dispatch_out[b] = 1.0f;
            combine_out[b]  = p;
        }
    }

    // scalar finalize from folded partials (sAccF written pre-sync by this block)
    if (blockIdx.x == 0 && threadIdx.x == 0) {
        float z_loss = sAccF[0] / (float)N;

        float aux = 0.f;
        for (int e = 0; e < E; e++) aux += sAccF[9 + e] * sAccF[1 + e];
        aux = aux * (float)E / ((float)N * (float)N);

        float G[E][E];
        int t = 0;
        for (int a = 0; a < E; a++)
            for (int b = a; b < E; b++) { G[a][b] = sAccF[17 + t]; G[b][a] = sAccF[17 + t]; t++; }
        float nrm[E];
        for (int a = 0; a < E; a++) nrm[a] = fmaxf(sqrtf(G[a][a]), 1e-12f);
        float div = 0.f;
        for (int a = 0; a < E; a++)
            for (int b = a + 1; b < E; b++) {
                float c = G[a][b] / (nrm[a] * nrm[b]);
                div += 2.0f * c * c;
            }
        div /= (float)(E * (E - 1));

        double M = (double)N * E;
        double sm = (double)sAccF[53], sq = (double)sAccF[54];
        double var = (sq - sm * sm / M) / (M - 1.0);

        scalars_out[0] = z_loss;
        scalars_out[1] = aux;
        scalars_out[2] = div;
        scalars_out[3] = (float)sqrt(var);
    }
}

// -------------------------------------------------------------- launch ----
extern "C" void kernel_launch(void* const* d_in, const int* in_sizes, int n_in,
                              void* d_out, int out_size) {
    const float* logits = (const float*)d_in[1];
    int N = in_sizes[1] / E;                              // 8192
    int Ccap = (int)((3 * N + 2 * E - 1) / (2 * E));      // ceil(1.5*N/E) = 1536
    if (Ccap < 1) Ccap = 1;

    float* out = (float*)d_out;
    size_t D = (size_t)N * E * (size_t)Ccap;
    float* dispatch_out = out;
    float* combine_out  = out + D;
    float* scalars_out  = out + 2 * D;

    // 1) fused: token (32 blocks) || zero-fill (2368 blocks)
    size_t n4 = (size_t)out_size >> 2;
    fill_token_kernel<<<TBLOCKS + FBLOCKS, 256>>>((uint4*)d_out, n4, logits, N);
    size_t rem = (size_t)out_size & 3;
    if (rem) cudaMemsetAsync((float*)d_out + (out_size - rem), 0, rem * sizeof(float));

    // 2) fold + rank + scatter + scalars
    static bool attr_set = false;
    if (!attr_set) {
        cudaFuncSetAttribute(rank_scatter_kernel,
                             cudaFuncAttributeMaxDynamicSharedMemorySize,
                             MAXN * (int)sizeof(unsigned long long));
        attr_set = true;
    }
    int rblocks = (N + 31) / 32;                          // 8 warps x 4 tokens
    rank_scatter_kernel<<<rblocks, 256, MAXN * sizeof(unsigned long long)>>>(
        dispatch_out, combine_out, scalars_out, N, Ccap);
}

// round 5
// speedup vs baseline: 1.0195x; 1.0195x over previous
#include <cuda_runtime.h>
#include <cstdint>
#include <cstddef>

// Router: top-1 MoE routing with capacity constraint.
// Outputs (float32): dispatch[N,8,Ccap], combine[N,8,Ccap], z, aux, div, std
//
// Fork-join graph:
//   main stream : fill_kernel (805MB zero fill, DRAM roofline ~115us)
//   side stream : token_kernel -> rank_kernel   (hidden under the fill)
//   join        : scatter_kernel (<=16K sparse stores + scalars, ~3us)

#define E 8
#define MAXN 8192
#define NACC 55   // 0:z  1..8:psum  9..16:cnt  17..52:G(upper tri 36)  53:sum  54:sumsq
#define TBLOCKS 32
#define FBLOCKS 2368

__device__ unsigned long long g_fkey[MAXN];   // [e:3][p_bits:32][invidx:13]
__device__ float g_prob[MAXN];
__device__ int   g_rank[MAXN];
__device__ float g_part[TBLOCKS][NACC];

// ---------------------------------------------------------------- fill ----
__global__ void fill_kernel(uint4* __restrict__ out, size_t n4) {
    const uint4 z = make_uint4(0u, 0u, 0u, 0u);
    size_t i = (size_t)blockIdx.x * blockDim.x + threadIdx.x;
    size_t stride = (size_t)gridDim.x * blockDim.x;
    for (; i < n4; i += stride) out[i] = z;
}

// --------------------------------------------------------------- token ----
__global__ void token_kernel(const float* __restrict__ logits, int N) {
    int i = blockIdx.x * blockDim.x + threadIdx.x;
    float vals[NACC];
#pragma unroll
    for (int k = 0; k < NACC; k++) vals[k] = 0.0f;

    if (i < N) {
        float4 r0 = reinterpret_cast<const float4*>(logits)[2 * i + 0];
        float4 r1 = reinterpret_cast<const float4*>(logits)[2 * i + 1];
        float raw[E] = {r0.x, r0.y, r0.z, r0.w, r1.x, r1.y, r1.z, r1.w};

        float l[E];
        float s = 0.f, s2 = 0.f;
#pragma unroll
        for (int j = 0; j < E; j++) {
            s  += raw[j];
            s2 += raw[j] * raw[j];
            float c = fminf(fmaxf(raw[j], -10.0f), 10.0f);
            l[j] = c / 1.5f;                 // IEEE div, matches JAX clip/temp
        }
        vals[53] = s;
        vals[54] = s2;

        // argmax (first max)
        float m = l[0]; int e = 0;
#pragma unroll
        for (int j = 1; j < E; j++) {
            if (l[j] > m) { m = l[j]; e = j; }
        }

        float sumexp = 0.f;
        float ex[E];
#pragma unroll
        for (int j = 0; j < E; j++) { ex[j] = expf(l[j] - m); sumexp += ex[j]; }
#pragma unroll
        for (int j = 0; j < E; j++) vals[1 + j] = ex[j] / sumexp;

        // static-index one-hot (no local-memory spill)
#pragma unroll
        for (int j = 0; j < E; j++) vals[9 + j] = (e == j) ? 1.0f : 0.0f;

        float p = 1.0f / sumexp;             // probs[argmax] exactly as JAX
        g_prob[i] = p;
        // key: expert | prob bits | inverted index (branchless stable desc sort)
        unsigned long long key = (unsigned long long)__float_as_uint(p);
        g_fkey[i] = ((unsigned long long)e << 45) | (key << 13)
                  | (unsigned long long)(unsigned)(MAXN - 1 - i);

        float lse = m + logf(sumexp);
        vals[0] = lse * lse;

        int t = 0;
#pragma unroll
        for (int a = 0; a < E; a++)
#pragma unroll
            for (int b = a; b < E; b++) vals[17 + t++] = l[a] * l[b];
    }

    int lane = threadIdx.x & 31;
    int wid  = threadIdx.x >> 5;
#pragma unroll
    for (int k = 0; k < NACC; k++) {
        float v = vals[k];
        v += __shfl_down_sync(0xffffffffu, v, 16);
        v += __shfl_down_sync(0xffffffffu, v, 8);
        v += __shfl_down_sync(0xffffffffu, v, 4);
        v += __shfl_down_sync(0xffffffffu, v, 2);
        v += __shfl_down_sync(0xffffffffu, v, 1);
        vals[k] = v;
    }
    __shared__ float sAcc[8][NACC];
    if (lane == 0) {
#pragma unroll
        for (int k = 0; k < NACC; k++) sAcc[wid][k] = vals[k];
    }
    __syncthreads();
    for (int k = threadIdx.x; k < NACC; k += blockDim.x) {
        float v = 0.f;
#pragma unroll
        for (int w = 0; w < 8; w++) v += sAcc[w][k];
        g_part[blockIdx.x][k] = v;       // fully overwritten each replay: no init
    }
}

// ---------------------------------------------------------------- rank ----
// Block: 256 threads = 8 warps; each warp owns 4 tokens, lanes split the j loop.
// rank_i = #{j : fkey_j > fkey_i && fkey_j < (e_i+1)<<45}  (branchless, stable)
__global__ void rank_kernel(int N) {
    extern __shared__ unsigned long long sk[];   // MAXN * 8B = 64KB

    for (int k = threadIdx.x; k < MAXN; k += blockDim.x)
        sk[k] = (k < N) ? g_fkey[k] : 0ull;      // 0 never counts (fk > fki fails)
    __syncthreads();

    int lane = threadIdx.x & 31;
    int wid  = threadIdx.x >> 5;
    int base = (blockIdx.x * 8 + wid) * 4;

    unsigned long long fki[4], up[4];
    int cnt[4] = {0, 0, 0, 0};
#pragma unroll
    for (int t = 0; t < 4; t++) {
        int tok = base + t;
        unsigned long long f = (tok < N) ? sk[tok] : ~0ull;  // ~0: counts nothing
        fki[t] = f;
        up[t]  = (((f >> 45) + 1ull) << 45);
    }

    int n32 = MAXN >> 5;                         // 256 iterations per lane
#pragma unroll 8
    for (int it = 0; it < n32; ++it) {
        unsigned long long fk = sk[it * 32 + lane];
#pragma unroll
        for (int t = 0; t < 4; t++)
            cnt[t] += (int)((fk > fki[t]) & (fk < up[t]));
    }

#pragma unroll
    for (int t = 0; t < 4; t++) {
        int v = cnt[t];
        v += __shfl_down_sync(0xffffffffu, v, 16);
        v += __shfl_down_sync(0xffffffffu, v, 8);
        v += __shfl_down_sync(0xffffffffu, v, 4);
        v += __shfl_down_sync(0xffffffffu, v, 2);
        v += __shfl_down_sync(0xffffffffu, v, 1);
        cnt[t] = v;                              // valid on lane 0
    }

    if (lane == 0) {
#pragma unroll
        for (int t = 0; t < 4; t++) {
            int tok = base + t;
            if (tok < N) g_rank[tok] = cnt[t];
        }
    }
}

// -------------------------------------------------------------- scatter ----
__global__ void scatter_kernel(float* __restrict__ dispatch_out,
                               float* __restrict__ combine_out,
                               float* __restrict__ scalars_out,
                               int N, int Ccap) {
    __shared__ float sAccF[NACC];

    int i = blockIdx.x * blockDim.x + threadIdx.x;
    if (i < N) {
        int rank = g_rank[i];
        if (rank < Ccap) {
            int e = (int)(g_fkey[i] >> 45);
            float p = g_prob[i];
            size_t b = ((size_t)i * E + e) * (size_t)Ccap + (size_t)rank;
            dispatch_out[b] = 1.0f;
            combine_out[b]  = p;
        }
    }

    if (blockIdx.x == 0) {
        if (threadIdx.x < NACC) {
            int k = threadIdx.x;
            float v = 0.f;
#pragma unroll
            for (int r = 0; r < TBLOCKS; r++) v += g_part[r][k];
            sAccF[k] = v;
        }
        __syncthreads();
        if (threadIdx.x == 0) {
            float z_loss = sAccF[0] / (float)N;

            float aux = 0.f;
            for (int e = 0; e < E; e++) aux += sAccF[9 + e] * sAccF[1 + e];
            aux = aux * (float)E / ((float)N * (float)N);

            float G[E][E];
            int t = 0;
            for (int a = 0; a < E; a++)
                for (int b = a; b < E; b++) { G[a][b] = sAccF[17 + t]; G[b][a] = sAccF[17 + t]; t++; }
            float nrm[E];
            for (int a = 0; a < E; a++) nrm[a] = fmaxf(sqrtf(G[a][a]), 1e-12f);
            float div = 0.f;
            for (int a = 0; a < E; a++)
                for (int b = a + 1; b < E; b++) {
                    float c = G[a][b] / (nrm[a] * nrm[b]);
                    div += 2.0f * c * c;
                }
            div /= (float)(E * (E - 1));

            double M = (double)N * E;
            double sm = (double)sAccF[53], sq = (double)sAccF[54];
            double var = (sq - sm * sm / M) / (M - 1.0);

            scalars_out[0] = z_loss;
            scalars_out[1] = aux;
            scalars_out[2] = div;
            scalars_out[3] = (float)sqrt(var);
        }
    }
}

// -------------------------------------------------------------- launch ----
extern "C" void kernel_launch(void* const* d_in, const int* in_sizes, int n_in,
                              void* d_out, int out_size) {
    const float* logits = (const float*)d_in[1];
    int N = in_sizes[1] / E;                              // 8192
    int Ccap = (int)((3 * N + 2 * E - 1) / (2 * E));      // ceil(1.5*N/E) = 1536
    if (Ccap < 1) Ccap = 1;

    float* out = (float*)d_out;
    size_t D = (size_t)N * E * (size_t)Ccap;
    float* dispatch_out = out;
    float* combine_out  = out + D;
    float* scalars_out  = out + 2 * D;

    // one-time setup on the first (non-captured) correctness call
    static cudaStream_t side = nullptr;
    static cudaEvent_t  ev_fork = nullptr, ev_join = nullptr;
    if (!side) {
        cudaStreamCreateWithFlags(&side, cudaStreamNonBlocking);
        cudaEventCreateWithFlags(&ev_fork, cudaEventDisableTiming);
        cudaEventCreateWithFlags(&ev_join, cudaEventDisableTiming);
        cudaFuncSetAttribute(rank_kernel,
                             cudaFuncAttributeMaxDynamicSharedMemorySize,
                             MAXN * (int)sizeof(unsigned long long));
    }

    // fork: side stream runs token -> rank while main stream fills
    cudaEventRecord(ev_fork, 0);
    cudaStreamWaitEvent(side, ev_fork, 0);

    token_kernel<<<TBLOCKS, 256, 0, side>>>(logits, N);
    int rblocks = (N + 31) / 32;                          // 256
    rank_kernel<<<rblocks, 256, MAXN * sizeof(unsigned long long), side>>>(N);
    cudaEventRecord(ev_join, side);

    // main stream: DRAM-roofline zero fill
    size_t n4 = (size_t)out_size >> 2;
    fill_kernel<<<FBLOCKS, 256>>>((uint4*)d_out, n4);
    size_t rem = (size_t)out_size & 3;
    if (rem) cudaMemsetAsync((float*)d_out + (out_size - rem), 0, rem * sizeof(float));

    // join: scatter only after both fill and rank are done
    cudaStreamWaitEvent(0, ev_join, 0);
    scatter_kernel<<<(N + 255) / 256, 256>>>(dispatch_out, combine_out,
                                             scalars_out, N, Ccap);
}